// round 2
// baseline (speedup 1.0000x reference)
#include <cuda_runtime.h>
#include <cuda_bf16.h>
#include <math.h>

// Problem constants
#define B_ 32
#define T_ 64
#define V_ 50257
#define E_ 256
#define H_ 512
#define G_ (4 * H_)      // 2048
#define M_ (T_ * B_)     // 2048 rows (t-major, b-minor)
#define H2_ (2 * H_)     // 1024

// Scratch (device globals; no allocation allowed)
__device__ float g_xseq[M_ * E_];      // 2 MB   gathered shifted embeddings
__device__ float g_gates[M_ * G_];     // 16 MB  x_gates + h_gates + biases
__device__ float g_hgates[B_ * G_];    // 256 KB features @ W_hh^T + b_hh
__device__ float g_hs[M_ * H_];        // 4 MB   hidden states h_t
__device__ float g_hid[M_ * H2_];      // 8 MB   hs @ W1^T + b1

// ---------------------------------------------------------------------------
// Kernel 1: gather shifted embedding rows. Row m = t*B + b uses token
// captions[b, t==0 ? 0 : t-1].
// ---------------------------------------------------------------------------
__global__ void gather_xseq_kernel(const float* __restrict__ emb,
                                   const int* __restrict__ captions) {
    int m = blockIdx.x;                  // 0..M_-1
    int b = m % B_;
    int t = m / B_;
    int tt = (t == 0) ? 0 : (t - 1);
    int tok = captions[b * T_ + tt];
    const float4* src = (const float4*)(emb + (size_t)tok * E_);
    float4* dst = (float4*)(g_xseq + (size_t)m * E_);
    for (int i = threadIdx.x; i < E_ / 4; i += blockDim.x) dst[i] = src[i];
}

// ---------------------------------------------------------------------------
// Kernel 2: h_gates[b][g] = features[b,:] . W_hh[g,:] + b_hh[g]
// One warp per output element (65536 outputs; coalesced row reads + shfl).
// ---------------------------------------------------------------------------
__global__ void hgates_kernel(const float* __restrict__ features,
                              const float* __restrict__ W_hh,
                              const float* __restrict__ b_hh) {
    int gwid = (blockIdx.x * blockDim.x + threadIdx.x) >> 5;
    int lane = threadIdx.x & 31;
    if (gwid >= B_ * G_) return;
    int b = gwid / G_;
    int g = gwid % G_;
    const float* w = W_hh + (size_t)g * H_;
    const float* f = features + (size_t)b * H_;
    float acc = 0.f;
    #pragma unroll 4
    for (int k = lane; k < H_; k += 32) acc = fmaf(f[k], w[k], acc);
    #pragma unroll
    for (int off = 16; off > 0; off >>= 1)
        acc += __shfl_xor_sync(0xffffffffu, acc, off);
    if (lane == 0) g_hgates[gwid] = acc + b_hh[g];
}

// ---------------------------------------------------------------------------
// Generic NT SGEMM: C[m][n] = sum_k A[m][k] * Bm[n][k]  (+ epilogue by MODE)
// A: Mdim x K row-major, Bm: Ndim x K row-major.
// BM=BN=128, BK=16, 256 threads, 8x8 per-thread tiles, float4 loads.
// Mdim % 128 == 0 and K % 16 == 0 are guaranteed for all call sites.
// MODE 0: C = g_gates; add bias (b_ih) + g_hgates[(m%B)*G + n]
// MODE 1: C = g_hid;   add bias (b1)
// MODE 2: C = d_out;   add bias (b2); store at [b][t][n], b=m%B, t=m/B
// ---------------------------------------------------------------------------
#define BM 128
#define BN 128
#define BK 16
#define TM 8
#define TN 8

template <int MODE>
__global__ __launch_bounds__(256) void gemm_nt_kernel(
    const float* __restrict__ A, const float* __restrict__ Bm,
    const float* __restrict__ bias, float* __restrict__ C,
    int Ndim, int K) {
    __shared__ float As[BK][BM];
    __shared__ float Bs[BK][BN];

    const int tid = threadIdx.x;
    const int tx = tid & 15;       // 0..15  -> n
    const int ty = tid >> 4;       // 0..15  -> m
    const int rowA0 = blockIdx.y * BM;
    const int rowB0 = blockIdx.x * BN;

    float acc[TM][TN];
    #pragma unroll
    for (int i = 0; i < TM; i++)
        #pragma unroll
        for (int j = 0; j < TN; j++) acc[i][j] = 0.f;

    for (int k0 = 0; k0 < K; k0 += BK) {
        // Load tiles: 128 rows x 16 k = 512 float4 each; 2 per thread.
        #pragma unroll
        for (int p = 0; p < 2; p++) {
            int f = tid + p * 256;
            int r = f >> 2;
            int k4 = (f & 3) << 2;
            float4 av = *(const float4*)(A + (size_t)(rowA0 + r) * K + k0 + k4);
            As[k4 + 0][r] = av.x;
            As[k4 + 1][r] = av.y;
            As[k4 + 2][r] = av.z;
            As[k4 + 3][r] = av.w;
            int nb = rowB0 + r;
            float4 bv = make_float4(0.f, 0.f, 0.f, 0.f);
            if (nb < Ndim)
                bv = *(const float4*)(Bm + (size_t)nb * K + k0 + k4);
            Bs[k4 + 0][r] = bv.x;
            Bs[k4 + 1][r] = bv.y;
            Bs[k4 + 2][r] = bv.z;
            Bs[k4 + 3][r] = bv.w;
        }
        __syncthreads();

        #pragma unroll
        for (int k = 0; k < BK; k++) {
            float a[TM], bb[TN];
            #pragma unroll
            for (int i = 0; i < TM; i += 4) {
                float4 v = *(const float4*)&As[k][ty * TM + i];
                a[i] = v.x; a[i + 1] = v.y; a[i + 2] = v.z; a[i + 3] = v.w;
            }
            #pragma unroll
            for (int j = 0; j < TN; j += 4) {
                float4 v = *(const float4*)&Bs[k][tx * TN + j];
                bb[j] = v.x; bb[j + 1] = v.y; bb[j + 2] = v.z; bb[j + 3] = v.w;
            }
            #pragma unroll
            for (int i = 0; i < TM; i++)
                #pragma unroll
                for (int j = 0; j < TN; j++)
                    acc[i][j] = fmaf(a[i], bb[j], acc[i][j]);
        }
        __syncthreads();
    }

    // Epilogue
    #pragma unroll
    for (int i = 0; i < TM; i++) {
        int m = rowA0 + ty * TM + i;
        #pragma unroll
        for (int j = 0; j < TN; j++) {
            int n = rowB0 + tx * TN + j;
            if (n < Ndim) {
                float v = acc[i][j] + bias[n];
                if (MODE == 0) {
                    C[(size_t)m * Ndim + n] = v + g_hgates[(m % B_) * G_ + n];
                } else if (MODE == 1) {
                    C[(size_t)m * Ndim + n] = v;
                } else {
                    int b = m % B_;
                    int t = m / B_;
                    C[((size_t)b * T_ + t) * V_ + n] = v;
                }
            }
        }
    }
}

// ---------------------------------------------------------------------------
// Kernel: the only truly sequential part — the cell-state recurrence.
// One thread per (b, h). T=64 elementwise steps; gates live in L2 (16 MB).
// ---------------------------------------------------------------------------
__device__ __forceinline__ float sigm(float x) { return 1.f / (1.f + expf(-x)); }

__global__ void scan_kernel() {
    int idx = blockIdx.x * blockDim.x + threadIdx.x;  // 0..B_*H_-1
    if (idx >= B_ * H_) return;
    int b = idx / H_;
    int h = idx % H_;
    float c = 0.f;
    #pragma unroll 4
    for (int t = 0; t < T_; t++) {
        const float* gp = g_gates + ((size_t)t * B_ + b) * G_;
        float ig = gp[h];
        float fg = gp[H_ + h];
        float gg = gp[2 * H_ + h];
        float og = gp[3 * H_ + h];
        c = sigm(fg) * c + sigm(ig) * tanhf(gg);
        g_hs[((size_t)t * B_ + b) * H_ + h] = sigm(og) * tanhf(c);
    }
}

// ---------------------------------------------------------------------------
// Launch
// ---------------------------------------------------------------------------
extern "C" void kernel_launch(void* const* d_in, const int* in_sizes, int n_in,
                              void* d_out, int out_size) {
    const float* features = (const float*)d_in[0];
    const int*   captions = (const int*)d_in[1];
    const float* emb      = (const float*)d_in[2];
    const float* W_ih     = (const float*)d_in[3];
    const float* W_hh     = (const float*)d_in[4];
    const float* b_ih     = (const float*)d_in[5];
    const float* b_hh     = (const float*)d_in[6];
    const float* W1       = (const float*)d_in[7];
    const float* b1       = (const float*)d_in[8];
    const float* W2       = (const float*)d_in[9];
    const float* b2       = (const float*)d_in[10];
    float* out = (float*)d_out;

    float* p_xseq;  cudaGetSymbolAddress((void**)&p_xseq,  g_xseq);
    float* p_gates; cudaGetSymbolAddress((void**)&p_gates, g_gates);
    float* p_hs;    cudaGetSymbolAddress((void**)&p_hs,    g_hs);
    float* p_hid;   cudaGetSymbolAddress((void**)&p_hid,   g_hid);

    // 1. Gather shifted embeddings
    gather_xseq_kernel<<<M_, 64>>>(emb, captions);

    // 2. h_gates (constant across time)
    hgates_kernel<<<(B_ * G_ * 32) / 256, 256>>>(features, W_hh, b_hh);

    // 3. x_gates GEMM (+ h_gates + b_ih fused in epilogue) -> g_gates
    {
        dim3 grid(G_ / BN, M_ / BM);
        gemm_nt_kernel<0><<<grid, 256>>>(p_xseq, W_ih, b_ih, p_gates, G_, E_);
    }

    // 4. Sequential cell recurrence -> g_hs
    scan_kernel<<<(B_ * H_) / 256, 256>>>();

    // 5. hid GEMM -> g_hid
    {
        dim3 grid(H2_ / BN, M_ / BM);
        gemm_nt_kernel<1><<<grid, 256>>>(p_hs, W1, b1, p_hid, H2_, H_);
    }

    // 6. logits GEMM -> out (B, T, V), bias b2, transpose handled in epilogue
    {
        dim3 grid((V_ + BN - 1) / BN, M_ / BM);
        gemm_nt_kernel<2><<<grid, 256>>>(p_hid, W2, b2, out, V_, H2_);
    }
}

// round 6
// speedup vs baseline: 2.5569x; 2.5569x over previous
#include <cuda_runtime.h>
#include <cuda_bf16.h>
#include <math.h>
#include <stdint.h>

// Problem constants
#define B_ 32
#define T_ 64
#define V_ 50257
#define E_ 256
#define H_ 512
#define G_ (4 * H_)      // 2048
#define M_ (T_ * B_)     // 2048
#define H2_ (2 * H_)     // 1024 (K of logits GEMM)

// Scratch (device globals; no allocation allowed)
__device__ float g_xseq[M_ * E_];            // gathered shifted embeddings
__device__ float g_gates[M_ * G_];           // gate preactivations
__device__ float g_hgates[B_ * G_];          // features @ W_hh^T + b_hh
__device__ float g_hs[M_ * H_];              // hidden states
__device__ __nv_bfloat16 g_hid_hi[M_ * H2_]; // hid split hi
__device__ __nv_bfloat16 g_hid_lo[M_ * H2_]; // hid split lo
__device__ __nv_bfloat16 g_w2_hi[(size_t)V_ * H2_]; // W2 split hi (103 MB)
__device__ __nv_bfloat16 g_w2_lo[(size_t)V_ * H2_]; // W2 split lo (103 MB)

// ---------------------------------------------------------------------------
// Helpers
// ---------------------------------------------------------------------------
__device__ __forceinline__ uint32_t s2u(const void* p) {
    uint32_t a;
    asm("{ .reg .u64 t; cvta.to.shared.u64 t, %1; cvt.u32.u64 %0, t; }"
        : "=r"(a) : "l"(p));
    return a;
}

#define SWZ(o) ((o) ^ (((o) >> 3) & 0x70))

__device__ __forceinline__ void cp16(uint32_t dst, const void* src) {
    asm volatile("cp.async.cg.shared.global [%0], [%1], 16;" :: "r"(dst), "l"(src));
}

__device__ __forceinline__ void ldsm4(uint32_t* r, uint32_t addr) {
    asm volatile("ldmatrix.sync.aligned.m8n8.x4.shared.b16 {%0,%1,%2,%3}, [%4];"
                 : "=r"(r[0]), "=r"(r[1]), "=r"(r[2]), "=r"(r[3]) : "r"(addr));
}

__device__ __forceinline__ void mma16816(float* c, const uint32_t* a,
                                         uint32_t b0, uint32_t b1) {
    asm volatile(
        "mma.sync.aligned.m16n8k16.row.col.f32.bf16.bf16.f32 "
        "{%0,%1,%2,%3}, {%4,%5,%6,%7}, {%8,%9}, {%0,%1,%2,%3};"
        : "+f"(c[0]), "+f"(c[1]), "+f"(c[2]), "+f"(c[3])
        : "r"(a[0]), "r"(a[1]), "r"(a[2]), "r"(a[3]), "r"(b0), "r"(b1));
}

// ---------------------------------------------------------------------------
// Gather shifted embedding rows
// ---------------------------------------------------------------------------
__global__ void gather_xseq_kernel(const float* __restrict__ emb,
                                   const int* __restrict__ captions) {
    int m = blockIdx.x;
    int b = m % B_;
    int t = m / B_;
    int tt = (t == 0) ? 0 : (t - 1);
    int tok = captions[b * T_ + tt];
    const float4* src = (const float4*)(emb + (size_t)tok * E_);
    float4* dst = (float4*)(g_xseq + (size_t)m * E_);
    for (int i = threadIdx.x; i < E_ / 4; i += blockDim.x) dst[i] = src[i];
}

// ---------------------------------------------------------------------------
// h_gates[b][g] = features[b,:] . W_hh[g,:] + b_hh[g]
// ---------------------------------------------------------------------------
__global__ void hgates_kernel(const float* __restrict__ features,
                              const float* __restrict__ W_hh,
                              const float* __restrict__ b_hh) {
    int gwid = (blockIdx.x * blockDim.x + threadIdx.x) >> 5;
    int lane = threadIdx.x & 31;
    if (gwid >= B_ * G_) return;
    int b = gwid / G_;
    int g = gwid % G_;
    const float* w = W_hh + (size_t)g * H_;
    const float* f = features + (size_t)b * H_;
    float acc = 0.f;
    #pragma unroll 4
    for (int k = lane; k < H_; k += 32) acc = fmaf(f[k], w[k], acc);
    #pragma unroll
    for (int off = 16; off > 0; off >>= 1)
        acc += __shfl_xor_sync(0xffffffffu, acc, off);
    if (lane == 0) g_hgates[gwid] = acc + b_hh[g];
}

// ---------------------------------------------------------------------------
// SIMT NT SGEMM for the two small GEMMs.
// MODE 0: C=g_gates, += bias + g_hgates.  MODE 1: write bf16 hi/lo split of v.
// ---------------------------------------------------------------------------
#define BM 128
#define BN 128
#define BK 16
#define TM 8
#define TN 8

template <int MODE>
__global__ __launch_bounds__(256) void gemm_nt_kernel(
    const float* __restrict__ A, const float* __restrict__ Bm,
    const float* __restrict__ bias, float* __restrict__ C,
    int Ndim, int K) {
    __shared__ float As[BK][BM];
    __shared__ float Bs[BK][BN];

    const int tid = threadIdx.x;
    const int tx = tid & 15;
    const int ty = tid >> 4;
    const int rowA0 = blockIdx.y * BM;
    const int rowB0 = blockIdx.x * BN;

    float acc[TM][TN];
    #pragma unroll
    for (int i = 0; i < TM; i++)
        #pragma unroll
        for (int j = 0; j < TN; j++) acc[i][j] = 0.f;

    for (int k0 = 0; k0 < K; k0 += BK) {
        #pragma unroll
        for (int p = 0; p < 2; p++) {
            int f = tid + p * 256;
            int r = f >> 2;
            int k4 = (f & 3) << 2;
            float4 av = *(const float4*)(A + (size_t)(rowA0 + r) * K + k0 + k4);
            As[k4 + 0][r] = av.x;
            As[k4 + 1][r] = av.y;
            As[k4 + 2][r] = av.z;
            As[k4 + 3][r] = av.w;
            float4 bv = *(const float4*)(Bm + (size_t)(rowB0 + r) * K + k0 + k4);
            Bs[k4 + 0][r] = bv.x;
            Bs[k4 + 1][r] = bv.y;
            Bs[k4 + 2][r] = bv.z;
            Bs[k4 + 3][r] = bv.w;
        }
        __syncthreads();

        #pragma unroll
        for (int k = 0; k < BK; k++) {
            float a[TM], bb[TN];
            #pragma unroll
            for (int i = 0; i < TM; i += 4) {
                float4 v = *(const float4*)&As[k][ty * TM + i];
                a[i] = v.x; a[i + 1] = v.y; a[i + 2] = v.z; a[i + 3] = v.w;
            }
            #pragma unroll
            for (int j = 0; j < TN; j += 4) {
                float4 v = *(const float4*)&Bs[k][tx * TN + j];
                bb[j] = v.x; bb[j + 1] = v.y; bb[j + 2] = v.z; bb[j + 3] = v.w;
            }
            #pragma unroll
            for (int i = 0; i < TM; i++)
                #pragma unroll
                for (int j = 0; j < TN; j++)
                    acc[i][j] = fmaf(a[i], bb[j], acc[i][j]);
        }
        __syncthreads();
    }

    #pragma unroll
    for (int i = 0; i < TM; i++) {
        int m = rowA0 + ty * TM + i;
        #pragma unroll
        for (int j = 0; j < TN; j++) {
            int n = rowB0 + tx * TN + j;
            float v = acc[i][j] + bias[n];
            if (MODE == 0) {
                C[(size_t)m * Ndim + n] = v + g_hgates[(m % B_) * G_ + n];
            } else {
                __nv_bfloat16 hv = __float2bfloat16(v);
                g_hid_hi[(size_t)m * Ndim + n] = hv;
                g_hid_lo[(size_t)m * Ndim + n] =
                    __float2bfloat16(v - __bfloat162float(hv));
            }
        }
    }
}

// ---------------------------------------------------------------------------
// Sequential cell recurrence
// ---------------------------------------------------------------------------
__device__ __forceinline__ float sigm(float x) { return 1.f / (1.f + expf(-x)); }

__global__ void scan_kernel() {
    int idx = blockIdx.x * blockDim.x + threadIdx.x;
    if (idx >= B_ * H_) return;
    int b = idx / H_;
    int h = idx % H_;
    float c = 0.f;
    #pragma unroll 4
    for (int t = 0; t < T_; t++) {
        const float* gp = g_gates + ((size_t)t * B_ + b) * G_;
        float ig = gp[h];
        float fg = gp[H_ + h];
        float gg = gp[2 * H_ + h];
        float og = gp[3 * H_ + h];
        c = sigm(fg) * c + sigm(ig) * tanhf(gg);
        g_hs[((size_t)t * B_ + b) * H_ + h] = sigm(og) * tanhf(c);
    }
}

// ---------------------------------------------------------------------------
// W2 fp32 -> bf16 hi/lo split. One block per vocab row; 256 threads x float4.
// ---------------------------------------------------------------------------
__global__ __launch_bounds__(256) void split_w2_kernel(const float* __restrict__ W2) {
    int row = blockIdx.x;
    int c4 = threadIdx.x;            // float4 index within row (1024/4 = 256)
    float4 v = *(const float4*)(W2 + (size_t)row * H2_ + c4 * 4);
    __nv_bfloat16 h0 = __float2bfloat16(v.x);
    __nv_bfloat16 h1 = __float2bfloat16(v.y);
    __nv_bfloat16 h2 = __float2bfloat16(v.z);
    __nv_bfloat16 h3 = __float2bfloat16(v.w);
    __nv_bfloat16 l0 = __float2bfloat16(v.x - __bfloat162float(h0));
    __nv_bfloat16 l1 = __float2bfloat16(v.y - __bfloat162float(h1));
    __nv_bfloat16 l2 = __float2bfloat16(v.z - __bfloat162float(h2));
    __nv_bfloat16 l3 = __float2bfloat16(v.w - __bfloat162float(h3));
    __nv_bfloat162* hi = (__nv_bfloat162*)g_w2_hi;
    __nv_bfloat162* lo = (__nv_bfloat162*)g_w2_lo;
    size_t i2 = (size_t)row * (H2_ / 2) + c4 * 2;
    hi[i2]     = __halves2bfloat162(h0, h1);
    hi[i2 + 1] = __halves2bfloat162(h2, h3);
    lo[i2]     = __halves2bfloat162(l0, l1);
    lo[i2 + 1] = __halves2bfloat162(l2, l3);
}

// ---------------------------------------------------------------------------
// Logits GEMM on mma.sync (bf16 HMMA, fp32 accum), emulated fp32 via
// 3 products: Ahi*Bhi + Ahi*Blo + Alo*Bhi.
// CTA: 128(M) x 256(N), K in 16 chunks of 64. 512 threads = 16 warps,
// warp tile m32 x n64. 2-stage cp.async pipeline, SW128 swizzled tiles.
// Stage layout: AHI 16K | ALO 16K | BHI 32K | BLO 32K = 96KB; 2 stages.
// ---------------------------------------------------------------------------
#define STAGE_B 98304
#define OFF_ALO 16384
#define OFF_BHI 32768
#define OFF_BLO 65536
#define SMEM_TOTAL_LOGITS (2 * STAGE_B)

__device__ __forceinline__ void load_chunk(uint32_t su, int tid, int m0, int n0,
                                           int ch, int st) {
    const uint32_t so = su + st * STAGE_B;
    const char* ahi = (const char*)g_hid_hi + (size_t)m0 * 2048 + ch * 128;
    const char* alo = (const char*)g_hid_lo + (size_t)m0 * 2048 + ch * 128;
    #pragma unroll
    for (int p = 0; p < 2; p++) {
        int idx = tid + p * 512;           // 0..1023 over 128 rows x 8 slots
        int r = idx >> 3, s = idx & 7;
        uint32_t d = SWZ(r * 128 + s * 16);
        cp16(so + d, ahi + (size_t)r * 2048 + s * 16);
        cp16(so + OFF_ALO + d, alo + (size_t)r * 2048 + s * 16);
    }
    const char* bhi = (const char*)g_w2_hi + ch * 128;
    const char* blo = (const char*)g_w2_lo + ch * 128;
    #pragma unroll
    for (int p = 0; p < 4; p++) {
        int idx = tid + p * 512;           // 0..2047 over 256 rows x 8 slots
        int r = idx >> 3, s = idx & 7;
        int rg = n0 + r;
        if (rg > V_ - 1) rg = V_ - 1;
        uint32_t d = SWZ(r * 128 + s * 16);
        cp16(so + OFF_BHI + d, bhi + (size_t)rg * 2048 + s * 16);
        cp16(so + OFF_BLO + d, blo + (size_t)rg * 2048 + s * 16);
    }
}

__global__ __launch_bounds__(512, 1) void logits_kernel(
    const float* __restrict__ b2, float* __restrict__ out) {
    extern __shared__ __align__(1024) char smem[];
    const uint32_t su = s2u(smem);
    const int tid = threadIdx.x;
    const int wid = tid >> 5;
    const int lane = tid & 31;
    const int wm = wid & 3;       // m-group (32 rows)
    const int wn = wid >> 2;      // n-group (64 cols)
    const int m0 = blockIdx.x * 128;
    const int n0 = blockIdx.y * 256;
    const int lr = lane & 15;     // ldmatrix row within 16
    const int lc = lane >> 4;     // ldmatrix 16B column group

    float acc[2][8][4];
    #pragma unroll
    for (int i = 0; i < 2; i++)
        #pragma unroll
        for (int j = 0; j < 8; j++)
            #pragma unroll
            for (int q = 0; q < 4; q++) acc[i][j][q] = 0.f;

    // Prologue: chunk 0 -> stage 0
    load_chunk(su, tid, m0, n0, 0, 0);
    asm volatile("cp.async.commit_group;" ::: "memory");

    for (int ch = 0; ch < 16; ch++) {
        const int st = ch & 1;
        if (ch < 15) {
            load_chunk(su, tid, m0, n0, ch + 1, st ^ 1);
            asm volatile("cp.async.commit_group;" ::: "memory");
            asm volatile("cp.async.wait_group 1;" ::: "memory");
        } else {
            asm volatile("cp.async.wait_group 0;" ::: "memory");
        }
        __syncthreads();

        const uint32_t so = su + st * STAGE_B;
        #pragma unroll
        for (int j = 0; j < 4; j++) {       // k16 steps within chunk of 64
            uint32_t ahi[2][4], alo[2][4];
            #pragma unroll
            for (int fm = 0; fm < 2; fm++) {
                int row = wm * 32 + fm * 16 + lr;
                uint32_t d = SWZ(row * 128 + (j * 2 + lc) * 16);
                ldsm4(ahi[fm], so + d);
                ldsm4(alo[fm], so + OFF_ALO + d);
            }
            #pragma unroll
            for (int fb = 0; fb < 4; fb++) { // each covers n16 -> 2 n8 frags
                int row = wn * 64 + fb * 16 + lr;
                uint32_t d = SWZ(row * 128 + (j * 2 + lc) * 16);
                uint32_t bh[4], bl[4];
                ldsm4(bh, so + OFF_BHI + d);
                ldsm4(bl, so + OFF_BLO + d);
                #pragma unroll
                for (int fm = 0; fm < 2; fm++) {
                    float* C0 = acc[fm][fb * 2];
                    float* C1 = acc[fm][fb * 2 + 1];
                    mma16816(C0, ahi[fm], bh[0], bh[2]);
                    mma16816(C1, ahi[fm], bh[1], bh[3]);
                    mma16816(C0, ahi[fm], bl[0], bl[2]);
                    mma16816(C1, ahi[fm], bl[1], bl[3]);
                    mma16816(C0, alo[fm], bh[0], bh[2]);
                    mma16816(C1, alo[fm], bh[1], bh[3]);
                }
            }
        }
        __syncthreads();
    }

    // Epilogue: fp32 accum -> out[b][t][v] with bias. m = (t*B+b) row index.
    // NOTE: V_ is odd, so output rows are only 4-byte aligned -> scalar stores.
    #pragma unroll
    for (int fm = 0; fm < 2; fm++) {
        #pragma unroll
        for (int rr = 0; rr < 2; rr++) {
            int m = m0 + wm * 32 + fm * 16 + rr * 8 + (lane >> 2);
            int bb = m & 31;
            int tt = m >> 5;
            float* orow = out + (size_t)(bb * T_ + tt) * V_;
            #pragma unroll
            for (int fn = 0; fn < 8; fn++) {
                int n = n0 + wn * 64 + fn * 8 + (lane & 3) * 2;
                float c0 = acc[fm][fn][rr * 2 + 0];
                float c1 = acc[fm][fn][rr * 2 + 1];
                if (n < V_)     orow[n]     = c0 + b2[n];
                if (n + 1 < V_) orow[n + 1] = c1 + b2[n + 1];
            }
        }
    }
}

// ---------------------------------------------------------------------------
// Launch
// ---------------------------------------------------------------------------
extern "C" void kernel_launch(void* const* d_in, const int* in_sizes, int n_in,
                              void* d_out, int out_size) {
    const float* features = (const float*)d_in[0];
    const int*   captions = (const int*)d_in[1];
    const float* emb      = (const float*)d_in[2];
    const float* W_ih     = (const float*)d_in[3];
    const float* W_hh     = (const float*)d_in[4];
    const float* b_ih     = (const float*)d_in[5];
    const float* b_hh     = (const float*)d_in[6];
    const float* W1       = (const float*)d_in[7];
    const float* b1       = (const float*)d_in[8];
    const float* W2       = (const float*)d_in[9];
    const float* b2       = (const float*)d_in[10];
    float* out = (float*)d_out;

    float* p_xseq;  cudaGetSymbolAddress((void**)&p_xseq,  g_xseq);
    float* p_gates; cudaGetSymbolAddress((void**)&p_gates, g_gates);
    float* p_hs;    cudaGetSymbolAddress((void**)&p_hs,    g_hs);

    cudaFuncSetAttribute(logits_kernel,
                         cudaFuncAttributeMaxDynamicSharedMemorySize,
                         SMEM_TOTAL_LOGITS);

    // 1. W2 split (independent; biggest prep cost)
    split_w2_kernel<<<V_, 256>>>(W2);

    // 2. Gather shifted embeddings
    gather_xseq_kernel<<<M_, 64>>>(emb, captions);

    // 3. h_gates (constant across time)
    hgates_kernel<<<(B_ * G_ * 32) / 256, 256>>>(features, W_hh, b_hh);

    // 4. x_gates GEMM (+ h_gates + b_ih) -> g_gates
    {
        dim3 grid(G_ / BN, M_ / BM);
        gemm_nt_kernel<0><<<grid, 256>>>(p_xseq, W_ih, b_ih, p_gates, G_, E_);
    }

    // 5. Sequential cell recurrence -> g_hs
    scan_kernel<<<(B_ * H_) / 256, 256>>>();

    // 6. hid GEMM -> bf16 hi/lo split directly
    {
        dim3 grid(H2_ / BN, M_ / BM);
        gemm_nt_kernel<1><<<grid, 256>>>(p_hs, W1, b1, nullptr, H2_, H_);
    }

    // 7. Logits GEMM on HMMA (fused bias + [b][t][v] transpose store)
    {
        dim3 grid(M_ / 128, (V_ + 255) / 256);
        logits_kernel<<<grid, 512, SMEM_TOTAL_LOGITS>>>(b2, out);
    }
}

// round 14
// speedup vs baseline: 5.3312x; 2.0851x over previous
#include <cuda_runtime.h>
#include <cuda_bf16.h>
#include <cuda_fp16.h>
#include <math.h>
#include <stdint.h>

// Problem constants
#define B_ 32
#define T_ 64
#define V_ 50257
#define E_ 256
#define H_ 512
#define G_ (4 * H_)      // 2048
#define M_ (T_ * B_)     // 2048
#define H2_ (2 * H_)     // 1024 (K of logits GEMM)

// Scratch (device globals; no allocation allowed)
__device__ float g_xseq[M_ * E_];            // gathered shifted embeddings
__device__ float g_gates[M_ * G_];           // gate preactivations
__device__ float g_hgates[B_ * G_];          // features @ W_hh^T + b_hh
__device__ float g_hs[M_ * H_];              // hidden states
__device__ __half g_hid_h[M_ * H2_];         // hid in fp16
__device__ __half g_w2_h[(size_t)V_ * H2_];  // W2 in fp16 (103 MB)

// ---------------------------------------------------------------------------
// Helpers
// ---------------------------------------------------------------------------
__device__ __forceinline__ uint32_t s2u(const void* p) {
    uint32_t a;
    asm("{ .reg .u64 t; cvta.to.shared.u64 t, %1; cvt.u32.u64 %0, t; }"
        : "=r"(a) : "l"(p));
    return a;
}

#define SWZ(o) ((o) ^ (((o) >> 3) & 0x70))

__device__ __forceinline__ void cp16(uint32_t dst, const void* src) {
    asm volatile("cp.async.cg.shared.global [%0], [%1], 16;" :: "r"(dst), "l"(src));
}

__device__ __forceinline__ void ldsm4(uint32_t* r, uint32_t addr) {
    asm volatile("ldmatrix.sync.aligned.m8n8.x4.shared.b16 {%0,%1,%2,%3}, [%4];"
                 : "=r"(r[0]), "=r"(r[1]), "=r"(r[2]), "=r"(r[3]) : "r"(addr));
}

__device__ __forceinline__ void mma16816(float* c, const uint32_t* a,
                                         uint32_t b0, uint32_t b1) {
    asm volatile(
        "mma.sync.aligned.m16n8k16.row.col.f32.f16.f16.f32 "
        "{%0,%1,%2,%3}, {%4,%5,%6,%7}, {%8,%9}, {%0,%1,%2,%3};"
        : "+f"(c[0]), "+f"(c[1]), "+f"(c[2]), "+f"(c[3])
        : "r"(a[0]), "r"(a[1]), "r"(a[2]), "r"(a[3]), "r"(b0), "r"(b1));
}

// ---------------------------------------------------------------------------
// Gather shifted embedding rows
// ---------------------------------------------------------------------------
__global__ void gather_xseq_kernel(const float* __restrict__ emb,
                                   const int* __restrict__ captions) {
    int m = blockIdx.x;
    int b = m % B_;
    int t = m / B_;
    int tt = (t == 0) ? 0 : (t - 1);
    int tok = captions[b * T_ + tt];
    const float4* src = (const float4*)(emb + (size_t)tok * E_);
    float4* dst = (float4*)(g_xseq + (size_t)m * E_);
    for (int i = threadIdx.x; i < E_ / 4; i += blockDim.x) dst[i] = src[i];
}

// ---------------------------------------------------------------------------
// h_gates[b][g] = features[b,:] . W_hh[g,:] + b_hh[g]
// ---------------------------------------------------------------------------
__global__ void hgates_kernel(const float* __restrict__ features,
                              const float* __restrict__ W_hh,
                              const float* __restrict__ b_hh) {
    int gwid = (blockIdx.x * blockDim.x + threadIdx.x) >> 5;
    int lane = threadIdx.x & 31;
    if (gwid >= B_ * G_) return;
    int b = gwid / G_;
    int g = gwid % G_;
    const float* w = W_hh + (size_t)g * H_;
    const float* f = features + (size_t)b * H_;
    float acc = 0.f;
    #pragma unroll 4
    for (int k = lane; k < H_; k += 32) acc = fmaf(f[k], w[k], acc);
    #pragma unroll
    for (int off = 16; off > 0; off >>= 1)
        acc += __shfl_xor_sync(0xffffffffu, acc, off);
    if (lane == 0) g_hgates[gwid] = acc + b_hh[g];
}

// ---------------------------------------------------------------------------
// SIMT NT SGEMM for the two small GEMMs.
// MODE 0: C=g_gates, += bias + g_hgates.  MODE 1: write fp16 hid.
// ---------------------------------------------------------------------------
#define BM 128
#define BN 128
#define BK 16
#define TM 8
#define TN 8

template <int MODE>
__global__ __launch_bounds__(256) void gemm_nt_kernel(
    const float* __restrict__ A, const float* __restrict__ Bm,
    const float* __restrict__ bias, float* __restrict__ C,
    int Ndim, int K) {
    __shared__ float As[BK][BM];
    __shared__ float Bs[BK][BN];

    const int tid = threadIdx.x;
    const int tx = tid & 15;
    const int ty = tid >> 4;
    const int rowA0 = blockIdx.y * BM;
    const int rowB0 = blockIdx.x * BN;

    float acc[TM][TN];
    #pragma unroll
    for (int i = 0; i < TM; i++)
        #pragma unroll
        for (int j = 0; j < TN; j++) acc[i][j] = 0.f;

    for (int k0 = 0; k0 < K; k0 += BK) {
        #pragma unroll
        for (int p = 0; p < 2; p++) {
            int f = tid + p * 256;
            int r = f >> 2;
            int k4 = (f & 3) << 2;
            float4 av = *(const float4*)(A + (size_t)(rowA0 + r) * K + k0 + k4);
            As[k4 + 0][r] = av.x;
            As[k4 + 1][r] = av.y;
            As[k4 + 2][r] = av.z;
            As[k4 + 3][r] = av.w;
            float4 bv = *(const float4*)(Bm + (size_t)(rowB0 + r) * K + k0 + k4);
            Bs[k4 + 0][r] = bv.x;
            Bs[k4 + 1][r] = bv.y;
            Bs[k4 + 2][r] = bv.z;
            Bs[k4 + 3][r] = bv.w;
        }
        __syncthreads();

        #pragma unroll
        for (int k = 0; k < BK; k++) {
            float a[TM], bb[TN];
            #pragma unroll
            for (int i = 0; i < TM; i += 4) {
                float4 v = *(const float4*)&As[k][ty * TM + i];
                a[i] = v.x; a[i + 1] = v.y; a[i + 2] = v.z; a[i + 3] = v.w;
            }
            #pragma unroll
            for (int j = 0; j < TN; j += 4) {
                float4 v = *(const float4*)&Bs[k][tx * TN + j];
                bb[j] = v.x; bb[j + 1] = v.y; bb[j + 2] = v.z; bb[j + 3] = v.w;
            }
            #pragma unroll
            for (int i = 0; i < TM; i++)
                #pragma unroll
                for (int j = 0; j < TN; j++)
                    acc[i][j] = fmaf(a[i], bb[j], acc[i][j]);
        }
        __syncthreads();
    }

    #pragma unroll
    for (int i = 0; i < TM; i++) {
        int m = rowA0 + ty * TM + i;
        #pragma unroll
        for (int j = 0; j < TN; j++) {
            int n = rowB0 + tx * TN + j;
            float v = acc[i][j] + bias[n];
            if (MODE == 0) {
                C[(size_t)m * Ndim + n] = v + g_hgates[(m % B_) * G_ + n];
            } else {
                g_hid_h[(size_t)m * Ndim + n] = __float2half(v);
            }
        }
    }
}

// ---------------------------------------------------------------------------
// Sequential cell recurrence
// ---------------------------------------------------------------------------
__device__ __forceinline__ float sigm(float x) { return 1.f / (1.f + expf(-x)); }

__global__ void scan_kernel() {
    int idx = blockIdx.x * blockDim.x + threadIdx.x;
    if (idx >= B_ * H_) return;
    int b = idx / H_;
    int h = idx % H_;
    float c = 0.f;
    #pragma unroll 4
    for (int t = 0; t < T_; t++) {
        const float* gp = g_gates + ((size_t)t * B_ + b) * G_;
        float ig = gp[h];
        float fg = gp[H_ + h];
        float gg = gp[2 * H_ + h];
        float og = gp[3 * H_ + h];
        c = sigm(fg) * c + sigm(ig) * tanhf(gg);
        g_hs[((size_t)t * B_ + b) * H_ + h] = sigm(og) * tanhf(c);
    }
}

// ---------------------------------------------------------------------------
// W2 fp32 -> fp16 convert. One block per vocab row; 256 threads x float4.
// ---------------------------------------------------------------------------
__global__ __launch_bounds__(256) void cvt_w2_kernel(const float* __restrict__ W2) {
    int row = blockIdx.x;
    int c4 = threadIdx.x;            // float4 index within row (1024/4 = 256)
    float4 v = *(const float4*)(W2 + (size_t)row * H2_ + c4 * 4);
    __half2* dst = (__half2*)g_w2_h;
    size_t i2 = (size_t)row * (H2_ / 2) + c4 * 2;
    dst[i2]     = __floats2half2_rn(v.x, v.y);
    dst[i2 + 1] = __floats2half2_rn(v.z, v.w);
}

// ---------------------------------------------------------------------------
// Logits GEMM on mma.sync (fp16 HMMA, fp32 accum), single product.
// CTA: 128(M) x 256(N), K in 16 chunks of 64. 512 threads = 16 warps,
// warp tile m32 x n64. 2-stage cp.async pipeline, SW128 swizzled tiles.
// Stage layout: A 16K | B 32K = 48KB; 2 stages = 96KB.
// ---------------------------------------------------------------------------
#define STAGE_B 49152
#define OFF_BH 16384
#define SMEM_TOTAL_LOGITS (2 * STAGE_B)

__device__ __forceinline__ void load_chunk(uint32_t su, int tid, int m0, int n0,
                                           int ch, int st) {
    const uint32_t so = su + st * STAGE_B;
    // A: 128 rows x 64 fp16 cols = 128B/row -> 1024 16B transfers
    const char* ah = (const char*)g_hid_h + (size_t)m0 * 2048 + ch * 128;
    #pragma unroll
    for (int p = 0; p < 2; p++) {
        int idx = tid + p * 512;            // 0..1023 over 128 rows x 8 slots
        int r = idx >> 3, s = idx & 7;
        uint32_t d = SWZ(r * 128 + s * 16);
        cp16(so + d, ah + (size_t)r * 2048 + s * 16);
    }
    // B: 256 rows x 64 fp16 cols -> 2048 16B transfers
    const char* bh = (const char*)g_w2_h + ch * 128;
    #pragma unroll
    for (int p = 0; p < 4; p++) {
        int idx = tid + p * 512;            // 0..2047 over 256 rows x 8 slots
        int r = idx >> 3, s = idx & 7;
        int rg = n0 + r;
        if (rg > V_ - 1) rg = V_ - 1;
        uint32_t d = SWZ(r * 128 + s * 16);
        cp16(so + OFF_BH + d, bh + (size_t)rg * 2048 + s * 16);
    }
}

__global__ __launch_bounds__(512, 1) void logits_kernel(
    const float* __restrict__ b2, float* __restrict__ out) {
    extern __shared__ __align__(1024) char smem[];
    const uint32_t su = s2u(smem);
    const int tid = threadIdx.x;
    const int wid = tid >> 5;
    const int lane = tid & 31;
    const int wm = wid & 3;       // m-group (32 rows)
    const int wn = wid >> 2;      // n-group (64 cols)
    const int m0 = blockIdx.x * 128;
    const int n0 = blockIdx.y * 256;
    const int lr = lane & 15;     // ldmatrix row within 16
    const int lc = lane >> 4;     // ldmatrix 16B column group

    float acc[2][8][4];
    #pragma unroll
    for (int i = 0; i < 2; i++)
        #pragma unroll
        for (int j = 0; j < 8; j++)
            #pragma unroll
            for (int q = 0; q < 4; q++) acc[i][j][q] = 0.f;

    // Prologue: chunk 0 -> stage 0
    load_chunk(su, tid, m0, n0, 0, 0);
    asm volatile("cp.async.commit_group;" ::: "memory");

    for (int ch = 0; ch < 16; ch++) {
        const int st = ch & 1;
        if (ch < 15) {
            load_chunk(su, tid, m0, n0, ch + 1, st ^ 1);
            asm volatile("cp.async.commit_group;" ::: "memory");
            asm volatile("cp.async.wait_group 1;" ::: "memory");
        } else {
            asm volatile("cp.async.wait_group 0;" ::: "memory");
        }
        __syncthreads();

        const uint32_t so = su + st * STAGE_B;
        #pragma unroll
        for (int j = 0; j < 4; j++) {       // k16 steps within chunk of 64
            uint32_t a[2][4];
            #pragma unroll
            for (int fm = 0; fm < 2; fm++) {
                int row = wm * 32 + fm * 16 + lr;
                uint32_t d = SWZ(row * 128 + (j * 2 + lc) * 16);
                ldsm4(a[fm], so + d);
            }
            #pragma unroll
            for (int fb = 0; fb < 4; fb++) { // each covers n16 -> 2 n8 frags
                int row = wn * 64 + fb * 16 + lr;
                uint32_t d = SWZ(row * 128 + (j * 2 + lc) * 16);
                uint32_t bh[4];
                ldsm4(bh, so + OFF_BH + d);
                #pragma unroll
                for (int fm = 0; fm < 2; fm++) {
                    mma16816(acc[fm][fb * 2],     a[fm], bh[0], bh[2]);
                    mma16816(acc[fm][fb * 2 + 1], a[fm], bh[1], bh[3]);
                }
            }
        }
        __syncthreads();
    }

    // Epilogue: fp32 accum -> out[b][t][v] with bias. m = (t*B+b) row index.
    // NOTE: V_ is odd, so output rows are only 4-byte aligned -> scalar stores.
    #pragma unroll
    for (int fm = 0; fm < 2; fm++) {
        #pragma unroll
        for (int rr = 0; rr < 2; rr++) {
            int m = m0 + wm * 32 + fm * 16 + rr * 8 + (lane >> 2);
            int bb = m & 31;
            int tt = m >> 5;
            float* orow = out + (size_t)(bb * T_ + tt) * V_;
            #pragma unroll
            for (int fn = 0; fn < 8; fn++) {
                int n = n0 + wn * 64 + fn * 8 + (lane & 3) * 2;
                float c0 = acc[fm][fn][rr * 2 + 0];
                float c1 = acc[fm][fn][rr * 2 + 1];
                if (n < V_)     orow[n]     = c0 + b2[n];
                if (n + 1 < V_) orow[n + 1] = c1 + b2[n + 1];
            }
        }
    }
}

// ---------------------------------------------------------------------------
// Launch
// ---------------------------------------------------------------------------
extern "C" void kernel_launch(void* const* d_in, const int* in_sizes, int n_in,
                              void* d_out, int out_size) {
    const float* features = (const float*)d_in[0];
    const int*   captions = (const int*)d_in[1];
    const float* emb      = (const float*)d_in[2];
    const float* W_ih     = (const float*)d_in[3];
    const float* W_hh     = (const float*)d_in[4];
    const float* b_ih     = (const float*)d_in[5];
    const float* b_hh     = (const float*)d_in[6];
    const float* W1       = (const float*)d_in[7];
    const float* b1       = (const float*)d_in[8];
    const float* W2       = (const float*)d_in[9];
    const float* b2       = (const float*)d_in[10];
    float* out = (float*)d_out;

    float* p_xseq;  cudaGetSymbolAddress((void**)&p_xseq,  g_xseq);
    float* p_gates; cudaGetSymbolAddress((void**)&p_gates, g_gates);
    float* p_hs;    cudaGetSymbolAddress((void**)&p_hs,    g_hs);

    cudaFuncSetAttribute(logits_kernel,
                         cudaFuncAttributeMaxDynamicSharedMemorySize,
                         SMEM_TOTAL_LOGITS);

    // 1. W2 -> fp16 (independent; biggest prep cost)
    cvt_w2_kernel<<<V_, 256>>>(W2);

    // 2. Gather shifted embeddings
    gather_xseq_kernel<<<M_, 64>>>(emb, captions);

    // 3. h_gates (constant across time)
    hgates_kernel<<<(B_ * G_ * 32) / 256, 256>>>(features, W_hh, b_hh);

    // 4. x_gates GEMM (+ h_gates + b_ih) -> g_gates
    {
        dim3 grid(G_ / BN, M_ / BM);
        gemm_nt_kernel<0><<<grid, 256>>>(p_xseq, W_ih, b_ih, p_gates, G_, E_);
    }

    // 5. Sequential cell recurrence -> g_hs
    scan_kernel<<<(B_ * H_) / 256, 256>>>();

    // 6. hid GEMM -> fp16 hid directly
    {
        dim3 grid(H2_ / BN, M_ / BM);
        gemm_nt_kernel<1><<<grid, 256>>>(p_hs, W1, b1, nullptr, H2_, H_);
    }

    // 7. Logits GEMM on HMMA (fused bias + [b][t][v] transpose store)
    {
        dim3 grid(M_ / 128, (V_ + 255) / 256);
        logits_kernel<<<grid, 512, SMEM_TOTAL_LOGITS>>>(b2, out);
    }
}